// round 1
// baseline (speedup 1.0000x reference)
#include <cuda_runtime.h>

#define N_OBJ 50000
#define N_REL 200000
#define FEAT 1024
#define INTER 512
#define EMB 200
#define N_CLS 151
#define N_PRED 51

// ---------------- scratch (module-load allocated, allowed) ----------------
__device__ float g_obj_h1[N_OBJ * INTER];     // relu(obj_feats @ Wso1^T + b)
__device__ float g_rel_h1[N_REL * INTER];     // relu(rel_feats @ Wp1^T + b)
__device__ float g_so_inter[N_OBJ * EMB];
__device__ float g_pred_inter[N_REL * EMB];
__device__ float g_Acomb[N_OBJ * EMB];        // s_o_inter @ (Wpi_s+Wpi_o)^T
__device__ float g_tmpP[N_REL * EMB];         // pred_inter @ Wpi_p^T
__device__ float g_pred_af[N_REL * EMB];
__device__ float g_Bs[N_OBJ * EMB];           // s_o_out @ Wpo1_s^T
__device__ float g_Bo[N_OBJ * EMB];           // s_o_out @ Wpo1_o^T
__device__ float g_tmpQ[N_REL * EMB];         // pred_af @ Wpo1_p^T
__device__ float g_hpo[N_REL * EMB];
__device__ float g_Wso[EMB * EMB];            // Wpi[:,0:200] + Wpi[:,400:600]

// ---------------- generic SGEMM: C = act(A[M,K] @ W[N,K]^T + bias) --------
// 128x128 tile, BK=8, 256 threads, 8x8 per thread (4x4 fragments at +0/+64)
template<bool RELU, bool HAS_BIAS>
__global__ __launch_bounds__(256)
void sgemm_nt(const float* __restrict__ A, int lda,
              const float* __restrict__ W, int ldw,
              const float* __restrict__ bias,
              float* __restrict__ C, int ldc,
              int M, int N, int K)
{
    __shared__ float As[8][128];
    __shared__ float Ws[8][128];

    const int tid = threadIdx.x;
    const int tx = tid & 15;    // n
    const int ty = tid >> 4;    // m
    const int m0 = blockIdx.x * 128;
    const int n0 = blockIdx.y * 128;

    const int lr = tid >> 1;         // 0..127
    const int lc = (tid & 1) * 4;    // 0 or 4

    float acc[8][8];
#pragma unroll
    for (int i = 0; i < 8; i++)
#pragma unroll
        for (int j = 0; j < 8; j++) acc[i][j] = 0.f;

    const bool aValid = (m0 + lr) < M;
    const bool wValid = (n0 + lr) < N;
    const float* Aptr = A + (m0 + lr) * lda + lc;
    const float* Wptr = W + (n0 + lr) * ldw + lc;

    const float4 z4 = make_float4(0.f, 0.f, 0.f, 0.f);
    float4 av = aValid ? *(const float4*)(Aptr) : z4;
    float4 wv = wValid ? *(const float4*)(Wptr) : z4;

    for (int k0 = 0; k0 < K; k0 += 8) {
        As[lc + 0][lr] = av.x; As[lc + 1][lr] = av.y;
        As[lc + 2][lr] = av.z; As[lc + 3][lr] = av.w;
        Ws[lc + 0][lr] = wv.x; Ws[lc + 1][lr] = wv.y;
        Ws[lc + 2][lr] = wv.z; Ws[lc + 3][lr] = wv.w;
        __syncthreads();

        float4 av2 = z4, wv2 = z4;
        if (k0 + 8 < K) {
            if (aValid) av2 = *(const float4*)(Aptr + k0 + 8);
            if (wValid) wv2 = *(const float4*)(Wptr + k0 + 8);
        }

#pragma unroll
        for (int k = 0; k < 8; k++) {
            float a0[8], b0[8];
            *(float4*)&a0[0] = *(const float4*)&As[k][ty * 4];
            *(float4*)&a0[4] = *(const float4*)&As[k][64 + ty * 4];
            *(float4*)&b0[0] = *(const float4*)&Ws[k][tx * 4];
            *(float4*)&b0[4] = *(const float4*)&Ws[k][64 + tx * 4];
#pragma unroll
            for (int i = 0; i < 8; i++)
#pragma unroll
                for (int j = 0; j < 8; j++)
                    acc[i][j] = fmaf(a0[i], b0[j], acc[i][j]);
        }
        __syncthreads();
        av = av2; wv = wv2;
    }

    const int nA = n0 + tx * 4;
    const int nB = n0 + 64 + tx * 4;
    float4 bias0 = z4, bias1 = z4;
    if (HAS_BIAS) {
        if (nA < N) bias0 = *(const float4*)(bias + nA);
        if (nB < N) bias1 = *(const float4*)(bias + nB);
    }

#pragma unroll
    for (int i = 0; i < 8; i++) {
        const int m = m0 + ty * 4 + ((i < 4) ? i : (i + 60));
        if (m >= M) continue;
        if (nA < N) {
            float4 v = make_float4(acc[i][0] + bias0.x, acc[i][1] + bias0.y,
                                   acc[i][2] + bias0.z, acc[i][3] + bias0.w);
            if (RELU) { v.x = fmaxf(v.x, 0.f); v.y = fmaxf(v.y, 0.f);
                        v.z = fmaxf(v.z, 0.f); v.w = fmaxf(v.w, 0.f); }
            *(float4*)(C + m * ldc + nA) = v;
        }
        if (nB < N) {
            float4 v = make_float4(acc[i][4] + bias1.x, acc[i][5] + bias1.y,
                                   acc[i][6] + bias1.z, acc[i][7] + bias1.w);
            if (RELU) { v.x = fmaxf(v.x, 0.f); v.y = fmaxf(v.y, 0.f);
                        v.z = fmaxf(v.z, 0.f); v.w = fmaxf(v.w, 0.f); }
            *(float4*)(C + m * ldc + nB) = v;
        }
    }
}

// ---------------- small helper kernels ----------------
__global__ void combine_wpi(const float* __restrict__ Wpi, float* __restrict__ Wso)
{
    int t = blockIdx.x * blockDim.x + threadIdx.x;
    if (t >= EMB * EMB) return;
    int r = t / EMB, c = t % EMB;
    Wso[t] = Wpi[r * 600 + c] + Wpi[r * 600 + 400 + c];
}

// dst[r,:] = src[idx[r],:], row width EMB (50 float4)
__global__ void gather_rows_f4(const float* __restrict__ src, const int* __restrict__ idx,
                               float* __restrict__ dst, int nrows)
{
    const int C4 = EMB / 4;
    int t = blockIdx.x * blockDim.x + threadIdx.x;
    if (t >= nrows * C4) return;
    int r = t / C4, c = t % C4;
    ((float4*)dst)[t] = ((const float4*)src)[idx[r] * C4 + c];
}

// pred_af = relu(tmpP + Acomb[sub_ind] + bpi)
__global__ void fuse_pi(const float* __restrict__ tmpP, const float* __restrict__ Acomb,
                        const int* __restrict__ rel_inds, const float* __restrict__ bias,
                        float* __restrict__ out)
{
    const int C4 = EMB / 4;
    int t = blockIdx.x * blockDim.x + threadIdx.x;
    if (t >= N_REL * C4) return;
    int r = t / C4, c = t % C4;
    int s = rel_inds[r * 3 + 1];
    float4 p = ((const float4*)tmpP)[t];
    float4 a = ((const float4*)Acomb)[s * C4 + c];
    float4 b = ((const float4*)bias)[c];
    float4 v = make_float4(fmaxf(p.x + a.x + b.x, 0.f), fmaxf(p.y + a.y + b.y, 0.f),
                           fmaxf(p.z + a.z + b.z, 0.f), fmaxf(p.w + a.w + b.w, 0.f));
    ((float4*)out)[t] = v;
}

// hpo = relu(tmpQ + Bs[sub_ind] + Bo[obj_ind] + bpo1)
__global__ void fuse_po(const float* __restrict__ tmpQ, const float* __restrict__ Bsub,
                        const float* __restrict__ Bobj, const int* __restrict__ rel_inds,
                        const float* __restrict__ bias, float* __restrict__ out)
{
    const int C4 = EMB / 4;
    int t = blockIdx.x * blockDim.x + threadIdx.x;
    if (t >= N_REL * C4) return;
    int r = t / C4, c = t % C4;
    int s = rel_inds[r * 3 + 1];
    int o = rel_inds[r * 3 + 2];
    float4 q  = ((const float4*)tmpQ)[t];
    float4 bs = ((const float4*)Bsub)[s * C4 + c];
    float4 bo = ((const float4*)Bobj)[o * C4 + c];
    float4 b  = ((const float4*)bias)[c];
    float4 v = make_float4(fmaxf(q.x + bs.x + bo.x + b.x, 0.f),
                           fmaxf(q.y + bs.y + bo.y + b.y, 0.f),
                           fmaxf(q.z + bs.z + bo.z + b.z, 0.f),
                           fmaxf(q.w + bs.w + bo.w + b.w, 0.f));
    ((float4*)out)[t] = v;
}

// ---------------- host side ----------------
static float* symaddr(const void* sym)
{
    void* p = nullptr;
    cudaGetSymbolAddress(&p, sym);
    return (float*)p;
}

static void gemm(const float* A, int lda, const float* W, int ldw, const float* bias,
                 float* C, int ldc, int M, int N, int K, bool relu)
{
    dim3 grid((M + 127) / 128, (N + 127) / 128), block(256);
    if (relu) {
        sgemm_nt<true, true><<<grid, block>>>(A, lda, W, ldw, bias, C, ldc, M, N, K);
    } else if (bias) {
        sgemm_nt<false, true><<<grid, block>>>(A, lda, W, ldw, bias, C, ldc, M, N, K);
    } else {
        sgemm_nt<false, false><<<grid, block>>>(A, lda, W, ldw, nullptr, C, ldc, M, N, K);
    }
}

extern "C" void kernel_launch(void* const* d_in, const int* in_sizes, int n_in,
                              void* d_out, int out_size)
{
    (void)in_sizes; (void)n_in; (void)out_size;

    const float* obj_feats  = (const float*)d_in[1];
    const float* rel_feats  = (const float*)d_in[2];
    const int*   rel_inds   = (const int*)d_in[4];
    const int*   gt_rel     = (const int*)d_in[5];
    const int*   gt_obj     = (const int*)d_in[6];
    const float* obj_embed  = (const float*)d_in[7];
    const float* pred_embed = (const float*)d_in[8];
    const float* Wrs = (const float*)d_in[9];  const float* brs = (const float*)d_in[10];
    const float* Wos = (const float*)d_in[11]; const float* bos = (const float*)d_in[12];
    const float* Wso1= (const float*)d_in[13]; const float* bso1= (const float*)d_in[14];
    const float* Wso2= (const float*)d_in[15]; const float* bso2= (const float*)d_in[16];
    const float* Wsoo= (const float*)d_in[17]; const float* bsoo= (const float*)d_in[18];
    const float* Wp1 = (const float*)d_in[19]; const float* bp1 = (const float*)d_in[20];
    const float* Wp2 = (const float*)d_in[21]; const float* bp2 = (const float*)d_in[22];
    const float* Wpi = (const float*)d_in[23]; const float* bpi = (const float*)d_in[24];
    const float* Wpo1= (const float*)d_in[25]; const float* bpo1= (const float*)d_in[26];
    const float* Wpo2= (const float*)d_in[27]; const float* bpo2= (const float*)d_in[28];

    float* out = (float*)d_out;
    float* o_so_out   = out;                      // [50000,200]
    float* o_pred_out = out + 10000000;           // [200000,200]
    float* o_rel_sem  = out + 50000000;           // [200000,200]
    float* o_obj_sem  = out + 90000000;           // [50000,200]
    float* o_rel_gt   = out + 100000000;          // [51,200]
    float* o_obj_gt   = out + 100010200;          // [151,200]

    float* obj_h1    = symaddr(g_obj_h1);
    float* rel_h1    = symaddr(g_rel_h1);
    float* so_inter  = symaddr(g_so_inter);
    float* pred_inter= symaddr(g_pred_inter);
    float* Acomb     = symaddr(g_Acomb);
    float* tmpP      = symaddr(g_tmpP);
    float* pred_af   = symaddr(g_pred_af);
    float* Bs        = symaddr(g_Bs);
    float* Bo        = symaddr(g_Bo);
    float* tmpQ      = symaddr(g_tmpQ);
    float* hpo       = symaddr(g_hpo);
    float* Wso       = symaddr(g_Wso);

    // semantic tables (tiny GEMMs) + gathers
    gemm(pred_embed, EMB, Wrs, EMB, brs, o_rel_gt, EMB, N_PRED, EMB, EMB, false);
    gemm(obj_embed,  EMB, Wos, EMB, bos, o_obj_gt, EMB, N_CLS,  EMB, EMB, false);
    {
        int tR = N_REL * (EMB / 4);
        gather_rows_f4<<<(tR + 255) / 256, 256>>>(o_rel_gt, gt_rel, o_rel_sem, N_REL);
        int tO = N_OBJ * (EMB / 4);
        gather_rows_f4<<<(tO + 255) / 256, 256>>>(o_obj_gt, gt_obj, o_obj_sem, N_OBJ);
    }

    // object path
    gemm(obj_feats, FEAT, Wso1, FEAT, bso1, obj_h1, INTER, N_OBJ, INTER, FEAT, true);
    gemm(obj_h1, INTER, Wso2, INTER, bso2, so_inter, EMB, N_OBJ, EMB, INTER, true);
    gemm(so_inter, EMB, Wsoo, EMB, bsoo, o_so_out, EMB, N_OBJ, EMB, EMB, false);

    // relation path
    gemm(rel_feats, FEAT, Wp1, FEAT, bp1, rel_h1, INTER, N_REL, INTER, FEAT, true);
    gemm(rel_h1, INTER, Wp2, INTER, bp2, pred_inter, EMB, N_REL, EMB, INTER, true);

    // pred_inter_af = relu(concat(sub,pred,obj(sub!)) @ Wpi^T + bpi)
    //   factored: Acomb on 50k rows (sub and obj slices share the sub index -> sum weights)
    combine_wpi<<<(EMB * EMB + 255) / 256, 256>>>(Wpi, Wso);
    gemm(so_inter, EMB, Wso, EMB, nullptr, Acomb, EMB, N_OBJ, EMB, EMB, false);
    gemm(pred_inter, EMB, Wpi + EMB, 600, nullptr, tmpP, EMB, N_REL, EMB, EMB, false);
    {
        int t = N_REL * (EMB / 4);
        fuse_pi<<<(t + 255) / 256, 256>>>(tmpP, Acomb, rel_inds, bpi, pred_af);
    }

    // pred_out = (relu(concat(sub_out,pred_af,obj_out) @ Wpo1^T + bpo1)) @ Wpo2^T + bpo2
    gemm(o_so_out, EMB, Wpo1, 600, nullptr, Bs, EMB, N_OBJ, EMB, EMB, false);           // cols 0:200
    gemm(o_so_out, EMB, Wpo1 + 2 * EMB, 600, nullptr, Bo, EMB, N_OBJ, EMB, EMB, false); // cols 400:600
    gemm(pred_af, EMB, Wpo1 + EMB, 600, nullptr, tmpQ, EMB, N_REL, EMB, EMB, false);    // cols 200:400
    {
        int t = N_REL * (EMB / 4);
        fuse_po<<<(t + 255) / 256, 256>>>(tmpQ, Bs, Bo, rel_inds, bpo1, hpo);
    }
    gemm(hpo, EMB, Wpo2, EMB, bpo2, o_pred_out, EMB, N_REL, EMB, EMB, false);
}

// round 3
// speedup vs baseline: 1.9431x; 1.9431x over previous
#include <cuda_runtime.h>
#include <cuda_bf16.h>
#include <cstdint>
#include <cstring>

#define N_OBJ 50000
#define N_REL 200000
#define FEAT 1024
#define INTER 512
#define EMB 200
#define N_CLS 151
#define N_PRED 51

// ---------------- scratch (module-load allocated, allowed) ----------------
__device__ float g_obj_h1[N_OBJ * INTER];
__device__ float g_rel_h1[N_REL * INTER];
__device__ float g_so_inter[N_OBJ * EMB];
__device__ float g_pred_inter[N_REL * EMB];
__device__ float g_Acomb[N_OBJ * EMB];
__device__ float g_tmpP[N_REL * EMB];
__device__ float g_pred_af[N_REL * EMB];
__device__ float g_Bs[N_OBJ * EMB];
__device__ float g_Bo[N_OBJ * EMB];
__device__ float g_tmpQ[N_REL * EMB];
__device__ float g_hpo[N_REL * EMB];
__device__ float g_Wso[EMB * EMB];

// ---------------- helpers ----------------
__device__ __forceinline__ uint32_t smem_u32(const void* p) {
    uint32_t a;
    asm("{ .reg .u64 t; cvta.to.shared.u64 t, %1; cvt.u32.u64 %0, t; }" : "=r"(a) : "l"(p));
    return a;
}

__device__ __forceinline__ void ldsm_x4(uint32_t& r0, uint32_t& r1, uint32_t& r2, uint32_t& r3,
                                        uint32_t addr) {
    asm volatile("ldmatrix.sync.aligned.m8n8.x4.shared.b16 {%0,%1,%2,%3}, [%4];"
                 : "=r"(r0), "=r"(r1), "=r"(r2), "=r"(r3) : "r"(addr));
}

__device__ __forceinline__ void mma_bf16(float* c, const uint32_t* a, uint32_t b0, uint32_t b1) {
    asm volatile("mma.sync.aligned.m16n8k16.row.col.f32.bf16.bf16.f32 "
                 "{%0,%1,%2,%3}, {%4,%5,%6,%7}, {%8,%9}, {%0,%1,%2,%3};"
                 : "+f"(c[0]), "+f"(c[1]), "+f"(c[2]), "+f"(c[3])
                 : "r"(a[0]), "r"(a[1]), "r"(a[2]), "r"(a[3]), "r"(b0), "r"(b1));
}

// split a float4 into hi/lo bf16x2 pairs and store 8B to each tile
__device__ __forceinline__ void store_hilo(uint32_t phi, uint32_t plo, float4 v) {
    __nv_bfloat162 h01 = __floats2bfloat162_rn(v.x, v.y);
    __nv_bfloat162 h23 = __floats2bfloat162_rn(v.z, v.w);
    float lx = v.x - __bfloat162float(h01.x);
    float ly = v.y - __bfloat162float(h01.y);
    float lz = v.z - __bfloat162float(h23.x);
    float lw = v.w - __bfloat162float(h23.y);
    __nv_bfloat162 l01 = __floats2bfloat162_rn(lx, ly);
    __nv_bfloat162 l23 = __floats2bfloat162_rn(lz, lw);
    uint32_t h0, h1, l0, l1;
    memcpy(&h0, &h01, 4); memcpy(&h1, &h23, 4);
    memcpy(&l0, &l01, 4); memcpy(&l1, &l23, 4);
    asm volatile("st.shared.v2.b32 [%0], {%1, %2};" :: "r"(phi), "r"(h0), "r"(h1) : "memory");
    asm volatile("st.shared.v2.b32 [%0], {%1, %2};" :: "r"(plo), "r"(l0), "r"(l1) : "memory");
}

// ---------------- HMMA bf16 split GEMM: C = act(A[M,K] @ W[N,K]^T + bias) --
// CTA tile 128x128, BK=32 fp32; 8 warps, warp tile 32(M) x 64(N)
// SMEM rows padded to 80B (40 bf16) -> conflict-free ldmatrix
#define ROWB 80
#define TILE_B (128 * ROWB)   // 10240 bytes per tile

__global__ __launch_bounds__(256)
void hmma_gemm(const float* __restrict__ A, int lda,
               const float* __restrict__ W, int ldw,
               const float* __restrict__ bias,
               float* __restrict__ C, int ldc,
               int M, int Ntot, int K, int relu, int has_bias)
{
    __shared__ __align__(16) char smem[4 * TILE_B];
    const uint32_t base = smem_u32(smem);
    const uint32_t sAh = base;
    const uint32_t sAl = base + TILE_B;
    const uint32_t sBh = base + 2 * TILE_B;
    const uint32_t sBl = base + 3 * TILE_B;

    const int tid = threadIdx.x;
    const int lane = tid & 31;
    const int wid = tid >> 5;
    const int wm = wid & 3;            // 4 M-warps * 32 rows
    const int wn = wid >> 2;           // 2 N-warps * 64 cols
    const int m0 = blockIdx.x * 128;
    const int n0 = blockIdx.y * 128;

    // ldmatrix per-lane addressing components
    const int lrA = (lane & 7) + ((lane >> 3) & 1) * 8;   // row 0..15
    const int wA  = lane >> 4;                            // k-word 0/1
    const int lrB = (lane & 7) + ((lane >> 4) << 3);      // row 0..15
    const int wB  = (lane >> 3) & 1;                      // k-word 0/1

    const int gid = lane >> 2, tig = lane & 3;

    float c[2][8][4];
#pragma unroll
    for (int i = 0; i < 2; i++)
#pragma unroll
        for (int j = 0; j < 8; j++)
#pragma unroll
            for (int q = 0; q < 4; q++) c[i][j][q] = 0.f;

    const int nkb = (K + 31) >> 5;

    // prefetch block 0
    float4 ra[4], rb[4];
#pragma unroll
    for (int i = 0; i < 4; i++) {
        int idx = tid + i * 256;
        int r = idx >> 3, c4 = idx & 7, gk = c4 * 4;
        ra[i] = (m0 + r < M && gk < K) ? *(const float4*)(A + (size_t)(m0 + r) * lda + gk)
                                       : make_float4(0.f, 0.f, 0.f, 0.f);
        rb[i] = (n0 + r < Ntot && gk < K) ? *(const float4*)(W + (size_t)(n0 + r) * ldw + gk)
                                          : make_float4(0.f, 0.f, 0.f, 0.f);
    }

    for (int kb = 0; kb < nkb; kb++) {
        // store current block (hi/lo split)
#pragma unroll
        for (int i = 0; i < 4; i++) {
            int idx = tid + i * 256;
            uint32_t off = (uint32_t)((idx >> 3) * ROWB + (idx & 7) * 8);
            store_hilo(sAh + off, sAl + off, ra[i]);
            store_hilo(sBh + off, sBl + off, rb[i]);
        }
        __syncthreads();

        // prefetch next block (overlaps MMA below)
        if (kb + 1 < nkb) {
            const int k0 = (kb + 1) << 5;
#pragma unroll
            for (int i = 0; i < 4; i++) {
                int idx = tid + i * 256;
                int r = idx >> 3, c4 = idx & 7, gk = k0 + c4 * 4;
                ra[i] = (m0 + r < M && gk < K) ? *(const float4*)(A + (size_t)(m0 + r) * lda + gk)
                                               : make_float4(0.f, 0.f, 0.f, 0.f);
                rb[i] = (n0 + r < Ntot && gk < K) ? *(const float4*)(W + (size_t)(n0 + r) * ldw + gk)
                                                  : make_float4(0.f, 0.f, 0.f, 0.f);
            }
        }

        // 3 passes: (Ah,Bh), (Ah,Bl), (Al,Bh)
#pragma unroll
        for (int pass = 0; pass < 3; pass++) {
            const uint32_t sA = (pass == 2) ? sAl : sAh;
            const uint32_t sB = (pass == 1) ? sBl : sBh;
#pragma unroll
            for (int kc = 0; kc < 2; kc++) {
                uint32_t a[2][4];
#pragma unroll
                for (int mt = 0; mt < 2; mt++) {
                    uint32_t addr = sA + (uint32_t)((wm * 32 + mt * 16 + lrA) * ROWB
                                                    + (2 * kc + wA) * 16);
                    ldsm_x4(a[mt][0], a[mt][1], a[mt][2], a[mt][3], addr);
                }
                uint32_t b[4][4];
#pragma unroll
                for (int ntt = 0; ntt < 4; ntt++) {
                    uint32_t addr = sB + (uint32_t)((wn * 64 + ntt * 16 + lrB) * ROWB
                                                    + (2 * kc + wB) * 16);
                    ldsm_x4(b[ntt][0], b[ntt][1], b[ntt][2], b[ntt][3], addr);
                }
#pragma unroll
                for (int mt = 0; mt < 2; mt++)
#pragma unroll
                    for (int nt = 0; nt < 8; nt++) {
                        const int ntt = nt >> 1, oct = nt & 1;
                        mma_bf16(c[mt][nt], a[mt], b[ntt][oct * 2], b[ntt][oct * 2 + 1]);
                    }
            }
        }
        __syncthreads();
    }

    // epilogue
#pragma unroll
    for (int nt = 0; nt < 8; nt++) {
        const int col = n0 + wn * 64 + nt * 8 + tig * 2;
        if (col >= Ntot) continue;
        float2 bb = make_float2(0.f, 0.f);
        if (has_bias) bb = *(const float2*)(bias + col);
#pragma unroll
        for (int mt = 0; mt < 2; mt++) {
            const int r0 = m0 + wm * 32 + mt * 16 + gid;
            float v0 = c[mt][nt][0] + bb.x, v1 = c[mt][nt][1] + bb.y;
            float v2 = c[mt][nt][2] + bb.x, v3 = c[mt][nt][3] + bb.y;
            if (relu) {
                v0 = fmaxf(v0, 0.f); v1 = fmaxf(v1, 0.f);
                v2 = fmaxf(v2, 0.f); v3 = fmaxf(v3, 0.f);
            }
            if (r0 < M)     *(float2*)(C + (size_t)r0 * ldc + col)       = make_float2(v0, v1);
            if (r0 + 8 < M) *(float2*)(C + (size_t)(r0 + 8) * ldc + col) = make_float2(v2, v3);
        }
    }
}

// ---------------- small helper kernels ----------------
__global__ void combine_wpi(const float* __restrict__ Wpi, float* __restrict__ Wso)
{
    int t = blockIdx.x * blockDim.x + threadIdx.x;
    if (t >= EMB * EMB) return;
    int r = t / EMB, c = t % EMB;
    Wso[t] = Wpi[r * 600 + c] + Wpi[r * 600 + 400 + c];
}

__global__ void gather_rows_f4(const float* __restrict__ src, const int* __restrict__ idx,
                               float* __restrict__ dst, int nrows)
{
    const int C4 = EMB / 4;
    int t = blockIdx.x * blockDim.x + threadIdx.x;
    if (t >= nrows * C4) return;
    int r = t / C4, c = t % C4;
    ((float4*)dst)[t] = ((const float4*)src)[idx[r] * C4 + c];
}

__global__ void fuse_pi(const float* __restrict__ tmpP, const float* __restrict__ Acomb,
                        const int* __restrict__ rel_inds, const float* __restrict__ bias,
                        float* __restrict__ out)
{
    const int C4 = EMB / 4;
    int t = blockIdx.x * blockDim.x + threadIdx.x;
    if (t >= N_REL * C4) return;
    int r = t / C4, c = t % C4;
    int s = rel_inds[r * 3 + 1];
    float4 p = ((const float4*)tmpP)[t];
    float4 a = ((const float4*)Acomb)[s * C4 + c];
    float4 b = ((const float4*)bias)[c];
    ((float4*)out)[t] = make_float4(
        fmaxf(p.x + a.x + b.x, 0.f), fmaxf(p.y + a.y + b.y, 0.f),
        fmaxf(p.z + a.z + b.z, 0.f), fmaxf(p.w + a.w + b.w, 0.f));
}

__global__ void fuse_po(const float* __restrict__ tmpQ, const float* __restrict__ Bsub,
                        const float* __restrict__ Bobj, const int* __restrict__ rel_inds,
                        const float* __restrict__ bias, float* __restrict__ out)
{
    const int C4 = EMB / 4;
    int t = blockIdx.x * blockDim.x + threadIdx.x;
    if (t >= N_REL * C4) return;
    int r = t / C4, c = t % C4;
    int s = rel_inds[r * 3 + 1];
    int o = rel_inds[r * 3 + 2];
    float4 q  = ((const float4*)tmpQ)[t];
    float4 bs = ((const float4*)Bsub)[s * C4 + c];
    float4 bo = ((const float4*)Bobj)[o * C4 + c];
    float4 b  = ((const float4*)bias)[c];
    ((float4*)out)[t] = make_float4(
        fmaxf(q.x + bs.x + bo.x + b.x, 0.f), fmaxf(q.y + bs.y + bo.y + b.y, 0.f),
        fmaxf(q.z + bs.z + bo.z + b.z, 0.f), fmaxf(q.w + bs.w + bo.w + b.w, 0.f));
}

// ---------------- host side ----------------
static float* symaddr(const void* sym)
{
    void* p = nullptr;
    cudaGetSymbolAddress(&p, sym);
    return (float*)p;
}

static void gemm(const float* A, int lda, const float* W, int ldw, const float* bias,
                 float* C, int ldc, int M, int N, int K, bool relu)
{
    dim3 grid((M + 127) / 128, (N + 127) / 128), block(256);
    hmma_gemm<<<grid, block>>>(A, lda, W, ldw, bias, C, ldc, M, N, K,
                               relu ? 1 : 0, bias ? 1 : 0);
}

extern "C" void kernel_launch(void* const* d_in, const int* in_sizes, int n_in,
                              void* d_out, int out_size)
{
    (void)in_sizes; (void)n_in; (void)out_size;

    const float* obj_feats  = (const float*)d_in[1];
    const float* rel_feats  = (const float*)d_in[2];
    const int*   rel_inds   = (const int*)d_in[4];
    const int*   gt_rel     = (const int*)d_in[5];
    const int*   gt_obj     = (const int*)d_in[6];
    const float* obj_embed  = (const float*)d_in[7];
    const float* pred_embed = (const float*)d_in[8];
    const float* Wrs = (const float*)d_in[9];  const float* brs = (const float*)d_in[10];
    const float* Wos = (const float*)d_in[11]; const float* bos = (const float*)d_in[12];
    const float* Wso1= (const float*)d_in[13]; const float* bso1= (const float*)d_in[14];
    const float* Wso2= (const float*)d_in[15]; const float* bso2= (const float*)d_in[16];
    const float* Wsoo= (const float*)d_in[17]; const float* bsoo= (const float*)d_in[18];
    const float* Wp1 = (const float*)d_in[19]; const float* bp1 = (const float*)d_in[20];
    const float* Wp2 = (const float*)d_in[21]; const float* bp2 = (const float*)d_in[22];
    const float* Wpi = (const float*)d_in[23]; const float* bpi = (const float*)d_in[24];
    const float* Wpo1= (const float*)d_in[25]; const float* bpo1= (const float*)d_in[26];
    const float* Wpo2= (const float*)d_in[27]; const float* bpo2= (const float*)d_in[28];

    float* out = (float*)d_out;
    float* o_so_out   = out;                      // [50000,200]
    float* o_pred_out = out + 10000000;           // [200000,200]
    float* o_rel_sem  = out + 50000000;           // [200000,200]
    float* o_obj_sem  = out + 90000000;           // [50000,200]
    float* o_rel_gt   = out + 100000000;          // [51,200]
    float* o_obj_gt   = out + 100010200;          // [151,200]

    float* obj_h1    = symaddr(g_obj_h1);
    float* rel_h1    = symaddr(g_rel_h1);
    float* so_inter  = symaddr(g_so_inter);
    float* pred_inter= symaddr(g_pred_inter);
    float* Acomb     = symaddr(g_Acomb);
    float* tmpP      = symaddr(g_tmpP);
    float* pred_af   = symaddr(g_pred_af);
    float* Bs        = symaddr(g_Bs);
    float* Bo        = symaddr(g_Bo);
    float* tmpQ      = symaddr(g_tmpQ);
    float* hpo       = symaddr(g_hpo);
    float* Wso       = symaddr(g_Wso);

    // semantic tables (tiny GEMMs) + gathers
    gemm(pred_embed, EMB, Wrs, EMB, brs, o_rel_gt, EMB, N_PRED, EMB, EMB, false);
    gemm(obj_embed,  EMB, Wos, EMB, bos, o_obj_gt, EMB, N_CLS,  EMB, EMB, false);
    {
        int tR = N_REL * (EMB / 4);
        gather_rows_f4<<<(tR + 255) / 256, 256>>>(o_rel_gt, gt_rel, o_rel_sem, N_REL);
        int tO = N_OBJ * (EMB / 4);
        gather_rows_f4<<<(tO + 255) / 256, 256>>>(o_obj_gt, gt_obj, o_obj_sem, N_OBJ);
    }

    // object path
    gemm(obj_feats, FEAT, Wso1, FEAT, bso1, obj_h1, INTER, N_OBJ, INTER, FEAT, true);
    gemm(obj_h1, INTER, Wso2, INTER, bso2, so_inter, EMB, N_OBJ, EMB, INTER, true);
    gemm(so_inter, EMB, Wsoo, EMB, bsoo, o_so_out, EMB, N_OBJ, EMB, EMB, false);

    // relation path
    gemm(rel_feats, FEAT, Wp1, FEAT, bp1, rel_h1, INTER, N_REL, INTER, FEAT, true);
    gemm(rel_h1, INTER, Wp2, INTER, bp2, pred_inter, EMB, N_REL, EMB, INTER, true);

    // pred_inter_af = relu(concat(sub,pred,obj(sub!)) @ Wpi^T + bpi), factored
    combine_wpi<<<(EMB * EMB + 255) / 256, 256>>>(Wpi, Wso);
    gemm(so_inter, EMB, Wso, EMB, nullptr, Acomb, EMB, N_OBJ, EMB, EMB, false);
    gemm(pred_inter, EMB, Wpi + EMB, 600, nullptr, tmpP, EMB, N_REL, EMB, EMB, false);
    {
        int t = N_REL * (EMB / 4);
        fuse_pi<<<(t + 255) / 256, 256>>>(tmpP, Acomb, rel_inds, bpi, pred_af);
    }

    // pred_out path, factored through 50k-row partials
    gemm(o_so_out, EMB, Wpo1, 600, nullptr, Bs, EMB, N_OBJ, EMB, EMB, false);
    gemm(o_so_out, EMB, Wpo1 + 2 * EMB, 600, nullptr, Bo, EMB, N_OBJ, EMB, EMB, false);
    gemm(pred_af, EMB, Wpo1 + EMB, 600, nullptr, tmpQ, EMB, N_REL, EMB, EMB, false);
    {
        int t = N_REL * (EMB / 4);
        fuse_po<<<(t + 255) / 256, 256>>>(tmpQ, Bs, Bo, rel_inds, bpo1, hpo);
    }
    gemm(hpo, EMB, Wpo2, EMB, bpo2, o_pred_out, EMB, N_REL, EMB, EMB, false);
}